// round 6
// baseline (speedup 1.0000x reference)
#include <cuda_runtime.h>

// CF_spikes: integrate-and-fire SNN, DURATION=16, THRESH=1.0
// B=32768, IN=784, H1=128, H2=64, OUT=10
//
// Feed-forward-in-time structure: encoder spikes depend only on features,
// s1 only on s0, etc.  So per layer we compute all 16 timesteps at once.

constexpr int kIN   = 784;
constexpr int kH1   = 128;
constexpr int kH2   = 64;
constexpr int kOUT  = 10;
constexpr int kT    = 16;
constexpr int kMT   = 16;      // batch rows per CTA
constexpr int kTHR  = 512;     // threads per CTA (128 h * 4 row-groups)
constexpr int kBMAX = 32768;

// Scratch (static __device__ arrays -- no runtime allocation)
__device__ float          g_W1T[kIN * kH1];                       // [j][h]
__device__ unsigned short g_mask[(long long)kBMAX * kIN];         // [b][j] 16-bit spike train

// ---------------------------------------------------------------------------
// Kernel 0: transpose W1 (H1 x IN, row-major) -> W1T (IN x H1)
// ---------------------------------------------------------------------------
__global__ void k_transpose(const float* __restrict__ W1) {
    int idx = blockIdx.x * blockDim.x + threadIdx.x;
    if (idx < kIN * kH1) {
        int j = idx / kH1;
        int h = idx - j * kH1;
        g_W1T[idx] = W1[h * kIN + j];
    }
}

// ---------------------------------------------------------------------------
// Kernel 1: encoder spike masks.  Bit-exact replication of the reference's
// fp32 accumulate / threshold / soft-reset loop, elementwise.
// ---------------------------------------------------------------------------
__global__ void k_encode(const float* __restrict__ feat, int B) {
    long long idx = (long long)blockIdx.x * blockDim.x + threadIdx.x;
    if (idx < (long long)B * kIN) {
        float f = feat[idx];
        float a = 0.0f;
        unsigned m = 0;
        #pragma unroll
        for (int t = 0; t < kT; t++) {
            a += f;
            if (a >= 1.0f) { m |= (1u << t); a -= 1.0f; }
        }
        g_mask[idx] = (unsigned short)m;
    }
}

// ---------------------------------------------------------------------------
// Kernel 2: fused layers 1..3 + output.  16 rows per CTA.
//   Layer 1: thread (h, rg) owns hidden unit h for 4 rows; accumulates
//            U[4 rows][16 t] in registers while streaming W1T once.
//   Membrane dynamics per layer in registers; spike masks exchanged via SMEM.
// ---------------------------------------------------------------------------
__global__ void __launch_bounds__(kTHR, 1)
k_main(const float* __restrict__ b1,
       const float* __restrict__ W2, const float* __restrict__ b2,
       const float* __restrict__ W3, const float* __restrict__ b3,
       const float* __restrict__ scale,
       float* __restrict__ out)
{
    __shared__ __align__(16) unsigned short sm_mask[kIN][kMT];  // 25088 B
    __shared__ __align__(16) unsigned short sm_s1[kH1][kMT];    //  4096 B
    __shared__ __align__(16) unsigned short sm_s2[kH2][kMT];    //  2048 B

    const int tid  = threadIdx.x;
    const int row0 = blockIdx.x * kMT;

    // Stage encoder masks for this row tile (coalesced reads, [j][r] layout)
    for (int i = tid; i < kIN * kMT; i += kTHR) {
        int r = i / kIN;
        int j = i - r * kIN;
        sm_mask[j][r] = g_mask[(long long)(row0 + r) * kIN + j];
    }
    __syncthreads();

    const int h     = tid & (kH1 - 1);   // hidden unit
    const int rg    = tid >> 7;          // row group 0..3 (uniform per warp)
    const int rbase = rg * 4;

    // ---- Layer 1 accumulation: all 16 timesteps at once ----
    float U[4][kT];
    #pragma unroll
    for (int r = 0; r < 4; r++)
        #pragma unroll
        for (int t = 0; t < kT; t++) U[r][t] = 0.0f;

    const float* wp = g_W1T + h;
    #pragma unroll 2
    for (int j = 0; j < kIN; j++) {
        float w = wp[j * kH1];                        // coalesced LDG
        unsigned long long mm =                        // broadcast LDS.64 (warp-uniform addr)
            *reinterpret_cast<const unsigned long long*>(&sm_mask[j][rbase]);
        unsigned lo = (unsigned)mm;
        unsigned hi = (unsigned)(mm >> 32);
        #pragma unroll
        for (int t = 0; t < kT; t++) {
            if (lo & (1u <<  t))       U[0][t] += w;
            if (lo & (1u << (t + 16))) U[1][t] += w;
            if (hi & (1u <<  t))       U[2][t] += w;
            if (hi & (1u << (t + 16))) U[3][t] += w;
        }
    }

    // ---- Layer 1 membrane dynamics -> s1 spike masks ----
    {
        const float bb = b1[h];
        #pragma unroll
        for (int r = 0; r < 4; r++) {
            float v = 0.0f; unsigned s = 0;
            #pragma unroll
            for (int t = 0; t < kT; t++) {
                v = (v + U[r][t]) + bb;               // matches (v + dot) + b
                if (v >= 1.0f) { s |= (1u << t); v -= 1.0f; }
            }
            sm_s1[h][rbase + r] = (unsigned short)s;
        }
    }
    __syncthreads();

    // ---- Layer 2: kH2*kMT = 1024 (h2, row) items over 512 threads ----
    #pragma unroll
    for (int k = 0; k < (kH2 * kMT) / kTHR; k++) {
        int item = tid + k * kTHR;
        int h2   = item >> 4;        // /kMT
        int r    = item & (kMT - 1);
        float acc[kT];
        #pragma unroll
        for (int t = 0; t < kT; t++) acc[t] = 0.0f;
        const float* w2p = W2 + h2 * kH1;
        for (int hh = 0; hh < kH1; hh++) {
            float w = w2p[hh];
            unsigned m = sm_s1[hh][r];
            #pragma unroll
            for (int t = 0; t < kT; t++)
                if (m & (1u << t)) acc[t] += w;
        }
        float v = 0.0f; unsigned s = 0;
        const float bb = b2[h2];
        #pragma unroll
        for (int t = 0; t < kT; t++) {
            v = (v + acc[t]) + bb;
            if (v >= 1.0f) { s |= (1u << t); v -= 1.0f; }
        }
        sm_s2[h2][r] = (unsigned short)s;
    }
    __syncthreads();

    // ---- Layer 3 + output: kOUT*kMT = 160 items ----
    if (tid < kOUT * kMT) {
        int o = tid >> 4;
        int r = tid & (kMT - 1);
        float acc[kT];
        #pragma unroll
        for (int t = 0; t < kT; t++) acc[t] = 0.0f;
        const float* w3p = W3 + o * kH2;
        for (int hh = 0; hh < kH2; hh++) {
            float w = w3p[hh];
            unsigned m = sm_s2[hh][r];
            #pragma unroll
            for (int t = 0; t < kT; t++)
                if (m & (1u << t)) acc[t] += w;
        }
        float v = 0.0f; int cnt = 0;
        const float bb = b3[o];
        #pragma unroll
        for (int t = 0; t < kT; t++) {
            v = (v + acc[t]) + bb;
            if (v >= 1.0f) { cnt++; v -= 1.0f; }
        }
        // counts/16 is exact (power of 2); then one fp32 multiply == reference
        out[(long long)(row0 + r) * kOUT + o] =
            ((float)cnt * (1.0f / 16.0f)) * scale[o];
    }
}

// ---------------------------------------------------------------------------
extern "C" void kernel_launch(void* const* d_in, const int* in_sizes, int n_in,
                              void* d_out, int out_size)
{
    const float* feat  = (const float*)d_in[0];
    const float* W1    = (const float*)d_in[1];
    const float* b1    = (const float*)d_in[2];
    const float* W2    = (const float*)d_in[3];
    const float* b2    = (const float*)d_in[4];
    const float* W3    = (const float*)d_in[5];
    const float* b3    = (const float*)d_in[6];
    const float* scale = (const float*)d_in[7];
    float*       out   = (float*)d_out;

    const int B = in_sizes[0] / kIN;   // 32768

    k_transpose<<<(kIN * kH1 + 255) / 256, 256>>>(W1);
    k_encode<<<(unsigned)((B * (long long)kIN + 255) / 256), 256>>>(feat, B);
    k_main<<<B / kMT, kTHR>>>(b1, W2, b2, W3, b3, scale, out);
}

// round 7
// speedup vs baseline: 1.0003x; 1.0003x over previous
#include <cuda_runtime.h>

// CF_spikes: integrate-and-fire SNN, DURATION=16, THRESH=1.0
// B=32768, IN=784, H1=128, H2=64, OUT=10
//
// Feed-forward-in-time structure: encoder spikes depend only on features,
// s1 only on s0, etc.  So per layer we compute all 16 timesteps at once.

constexpr int kIN   = 784;
constexpr int kH1   = 128;
constexpr int kH2   = 64;
constexpr int kOUT  = 10;
constexpr int kT    = 16;
constexpr int kMT   = 16;      // batch rows per CTA
constexpr int kTHR  = 512;     // threads per CTA (128 h * 4 row-groups)
constexpr int kBMAX = 32768;

// Scratch (static __device__ arrays -- no runtime allocation)
__device__ float          g_W1T[kIN * kH1];                       // [j][h]
__device__ unsigned short g_mask[(long long)kBMAX * kIN];         // [b][j] 16-bit spike train

// ---------------------------------------------------------------------------
// Kernel 0: transpose W1 (H1 x IN, row-major) -> W1T (IN x H1)
// ---------------------------------------------------------------------------
__global__ void k_transpose(const float* __restrict__ W1) {
    int idx = blockIdx.x * blockDim.x + threadIdx.x;
    if (idx < kIN * kH1) {
        int j = idx / kH1;
        int h = idx - j * kH1;
        g_W1T[idx] = W1[h * kIN + j];
    }
}

// ---------------------------------------------------------------------------
// Kernel 1: encoder spike masks.  Bit-exact replication of the reference's
// fp32 accumulate / threshold / soft-reset loop, elementwise.
// ---------------------------------------------------------------------------
__global__ void k_encode(const float* __restrict__ feat, int B) {
    long long idx = (long long)blockIdx.x * blockDim.x + threadIdx.x;
    if (idx < (long long)B * kIN) {
        float f = feat[idx];
        float a = 0.0f;
        unsigned m = 0;
        #pragma unroll
        for (int t = 0; t < kT; t++) {
            a += f;
            if (a >= 1.0f) { m |= (1u << t); a -= 1.0f; }
        }
        g_mask[idx] = (unsigned short)m;
    }
}

// ---------------------------------------------------------------------------
// Kernel 2: fused layers 1..3 + output.  16 rows per CTA.
//   Layer 1: thread (h, rg) owns hidden unit h for 4 rows; accumulates
//            U[4 rows][16 t] in registers while streaming W1T once.
//   Membrane dynamics per layer in registers; spike masks exchanged via SMEM.
// ---------------------------------------------------------------------------
__global__ void __launch_bounds__(kTHR, 1)
k_main(const float* __restrict__ b1,
       const float* __restrict__ W2, const float* __restrict__ b2,
       const float* __restrict__ W3, const float* __restrict__ b3,
       const float* __restrict__ scale,
       float* __restrict__ out)
{
    __shared__ __align__(16) unsigned short sm_mask[kIN][kMT];  // 25088 B
    __shared__ __align__(16) unsigned short sm_s1[kH1][kMT];    //  4096 B
    __shared__ __align__(16) unsigned short sm_s2[kH2][kMT];    //  2048 B

    const int tid  = threadIdx.x;
    const int row0 = blockIdx.x * kMT;

    // Stage encoder masks for this row tile (coalesced reads, [j][r] layout)
    for (int i = tid; i < kIN * kMT; i += kTHR) {
        int r = i / kIN;
        int j = i - r * kIN;
        sm_mask[j][r] = g_mask[(long long)(row0 + r) * kIN + j];
    }
    __syncthreads();

    const int h     = tid & (kH1 - 1);   // hidden unit
    const int rg    = tid >> 7;          // row group 0..3 (uniform per warp)
    const int rbase = rg * 4;

    // ---- Layer 1 accumulation: all 16 timesteps at once ----
    float U[4][kT];
    #pragma unroll
    for (int r = 0; r < 4; r++)
        #pragma unroll
        for (int t = 0; t < kT; t++) U[r][t] = 0.0f;

    const float* wp = g_W1T + h;
    #pragma unroll 2
    for (int j = 0; j < kIN; j++) {
        float w = wp[j * kH1];                        // coalesced LDG
        unsigned long long mm =                        // broadcast LDS.64 (warp-uniform addr)
            *reinterpret_cast<const unsigned long long*>(&sm_mask[j][rbase]);
        unsigned lo = (unsigned)mm;
        unsigned hi = (unsigned)(mm >> 32);
        #pragma unroll
        for (int t = 0; t < kT; t++) {
            if (lo & (1u <<  t))       U[0][t] += w;
            if (lo & (1u << (t + 16))) U[1][t] += w;
            if (hi & (1u <<  t))       U[2][t] += w;
            if (hi & (1u << (t + 16))) U[3][t] += w;
        }
    }

    // ---- Layer 1 membrane dynamics -> s1 spike masks ----
    {
        const float bb = b1[h];
        #pragma unroll
        for (int r = 0; r < 4; r++) {
            float v = 0.0f; unsigned s = 0;
            #pragma unroll
            for (int t = 0; t < kT; t++) {
                v = (v + U[r][t]) + bb;               // matches (v + dot) + b
                if (v >= 1.0f) { s |= (1u << t); v -= 1.0f; }
            }
            sm_s1[h][rbase + r] = (unsigned short)s;
        }
    }
    __syncthreads();

    // ---- Layer 2: kH2*kMT = 1024 (h2, row) items over 512 threads ----
    #pragma unroll
    for (int k = 0; k < (kH2 * kMT) / kTHR; k++) {
        int item = tid + k * kTHR;
        int h2   = item >> 4;        // /kMT
        int r    = item & (kMT - 1);
        float acc[kT];
        #pragma unroll
        for (int t = 0; t < kT; t++) acc[t] = 0.0f;
        const float* w2p = W2 + h2 * kH1;
        for (int hh = 0; hh < kH1; hh++) {
            float w = w2p[hh];
            unsigned m = sm_s1[hh][r];
            #pragma unroll
            for (int t = 0; t < kT; t++)
                if (m & (1u << t)) acc[t] += w;
        }
        float v = 0.0f; unsigned s = 0;
        const float bb = b2[h2];
        #pragma unroll
        for (int t = 0; t < kT; t++) {
            v = (v + acc[t]) + bb;
            if (v >= 1.0f) { s |= (1u << t); v -= 1.0f; }
        }
        sm_s2[h2][r] = (unsigned short)s;
    }
    __syncthreads();

    // ---- Layer 3 + output: kOUT*kMT = 160 items ----
    if (tid < kOUT * kMT) {
        int o = tid >> 4;
        int r = tid & (kMT - 1);
        float acc[kT];
        #pragma unroll
        for (int t = 0; t < kT; t++) acc[t] = 0.0f;
        const float* w3p = W3 + o * kH2;
        for (int hh = 0; hh < kH2; hh++) {
            float w = w3p[hh];
            unsigned m = sm_s2[hh][r];
            #pragma unroll
            for (int t = 0; t < kT; t++)
                if (m & (1u << t)) acc[t] += w;
        }
        float v = 0.0f; int cnt = 0;
        const float bb = b3[o];
        #pragma unroll
        for (int t = 0; t < kT; t++) {
            v = (v + acc[t]) + bb;
            if (v >= 1.0f) { cnt++; v -= 1.0f; }
        }
        // counts/16 is exact (power of 2); then one fp32 multiply == reference
        out[(long long)(row0 + r) * kOUT + o] =
            ((float)cnt * (1.0f / 16.0f)) * scale[o];
    }
}

// ---------------------------------------------------------------------------
extern "C" void kernel_launch(void* const* d_in, const int* in_sizes, int n_in,
                              void* d_out, int out_size)
{
    const float* feat  = (const float*)d_in[0];
    const float* W1    = (const float*)d_in[1];
    const float* b1    = (const float*)d_in[2];
    const float* W2    = (const float*)d_in[3];
    const float* b2    = (const float*)d_in[4];
    const float* W3    = (const float*)d_in[5];
    const float* b3    = (const float*)d_in[6];
    const float* scale = (const float*)d_in[7];
    float*       out   = (float*)d_out;

    const int B = in_sizes[0] / kIN;   // 32768

    k_transpose<<<(kIN * kH1 + 255) / 256, 256>>>(W1);
    k_encode<<<(unsigned)((B * (long long)kIN + 255) / 256), 256>>>(feat, B);
    k_main<<<B / kMT, kTHR>>>(b1, W2, b2, W3, b3, scale, out);
}